// round 6
// baseline (speedup 1.0000x reference)
#include <cuda_runtime.h>
#include <cuda_fp16.h>
#include <math.h>
#include <stdint.h>

#define S_LEN  128
#define B_SZ   32
#define NTOKR  4096      // S*B rows
#define NWE    512
#define D_T    64
#define H_RNN  1024
#define G4     4096      // 4*H
#define NVOCAB 32000

#define LO_SCALE     2048.0f
#define INV_LO_SCALE 4.8828125e-4f

// ------------------- scratch (device globals; no allocs allowed) -------------
__device__ float g_ht[B_SZ * D_T];
__device__ float g_vb[B_SZ * D_T];
__device__ float g_M[B_SZ * D_T * NWE];          // [b][i][k]  4MB
__device__ float g_emb[NTOKR * NWE];             // 8MB
__device__ float g_xp0[(size_t)NTOKR * G4];      // 64MB
__device__ float g_xp1[(size_t)NTOKR * G4];      // 64MB
__device__ float g_out0[NTOKR * H_RNN];          // 16MB
__device__ float g_out1[NTOKR * H_RNN];          // 16MB
__device__ float g_h[2][2][B_SZ * H_RNN];        // [layer][parity]
__device__ float g_c[2][B_SZ * H_RNN];
__device__ float g_gb0[G4];
__device__ float g_gb1[G4];
// fp16 hi/lo split scratch (lo pre-scaled by 2048)
__device__ __half g_Ah[(size_t)NTOKR * H_RNN];   // 8MB
__device__ __half g_Al[(size_t)NTOKR * H_RNN];   // 8MB
__device__ __half g_Bh[(size_t)NVOCAB * H_RNN];  // 62.5MB
__device__ __half g_Bl[(size_t)NVOCAB * H_RNN];  // 62.5MB

// ------------------------------- utility kernels -----------------------------
__global__ void zero_state_kernel() {
    int i = blockIdx.x * blockDim.x + threadIdx.x;
    if (i < B_SZ * H_RNN) {
        g_h[0][0][i] = 0.f; g_h[0][1][i] = 0.f;
        g_h[1][0][i] = 0.f; g_h[1][1][i] = 0.f;
        g_c[0][i] = 0.f;    g_c[1][i] = 0.f;
    }
}

__global__ void gbias_kernel(const float* __restrict__ bih0, const float* __restrict__ bhh0,
                             const float* __restrict__ bih1, const float* __restrict__ bhh1) {
    int g = blockIdx.x * blockDim.x + threadIdx.x;
    if (g < G4) {
        g_gb0[g] = bih0[g] + bhh0[g];
        g_gb1[g] = bih1[g] + bhh1[g];
    }
}

// fp32 -> fp16 hi + fp16 lo*2048 split (4 elements per thread)
__global__ void split_kernel(const float4* __restrict__ X, uint2* __restrict__ Hi,
                             uint2* __restrict__ Lo, int n4) {
    int i = blockIdx.x * 256 + threadIdx.x;
    if (i >= n4) return;
    float4 v = X[i];
    __half h0 = __float2half(v.x);
    __half h1 = __float2half(v.y);
    __half h2 = __float2half(v.z);
    __half h3 = __float2half(v.w);
    __half l0 = __float2half((v.x - __half2float(h0)) * LO_SCALE);
    __half l1 = __float2half((v.y - __half2float(h1)) * LO_SCALE);
    __half l2 = __float2half((v.z - __half2float(h2)) * LO_SCALE);
    __half l3 = __float2half((v.w - __half2float(h3)) * LO_SCALE);
    uint2 ph, pl;
    ph.x = (uint32_t)__half_as_ushort(h0) | ((uint32_t)__half_as_ushort(h1) << 16);
    ph.y = (uint32_t)__half_as_ushort(h2) | ((uint32_t)__half_as_ushort(h3) << 16);
    pl.x = (uint32_t)__half_as_ushort(l0) | ((uint32_t)__half_as_ushort(l1) << 16);
    pl.y = (uint32_t)__half_as_ushort(l2) | ((uint32_t)__half_as_ushort(l3) << 16);
    Hi[i] = ph;
    Lo[i] = pl;
}

// ht[b][i] = tanh(W2 @ tanh(ts*W1 + b1) + b2); vb[b][i] = sum_j trans_b[i*64+j]*ht[b][j]
__global__ void ht_kernel(const int* __restrict__ timestep,
                          const float* __restrict__ W1, const float* __restrict__ b1,
                          const float* __restrict__ W2, const float* __restrict__ b2,
                          const float* __restrict__ trans_b) {
    int b = blockIdx.x;
    int j = threadIdx.x;          // 64 threads
    float ts = (float)timestep[b] / 100.0f;
    __shared__ float h1[D_T];
    __shared__ float hts[D_T];
    h1[j] = tanhf(ts * W1[j] + b1[j]);
    __syncthreads();
    float acc = b2[j];
    #pragma unroll 8
    for (int k = 0; k < D_T; k++) acc += W2[j * D_T + k] * h1[k];
    float htv = tanhf(acc);
    g_ht[b * D_T + j] = htv;
    hts[j] = htv;
    __syncthreads();
    float vb = 0.f;
    #pragma unroll 8
    for (int k = 0; k < D_T; k++) vb += trans_b[j * D_T + k] * hts[k];
    g_vb[b * D_T + j] = vb;
}

// M[b][i][k] = sum_j ht[b][j] * trans_W[(i*64+j)*512 + k]
__global__ void M_kernel(const float* __restrict__ trans_W) {
    __shared__ float sht[B_SZ * D_T];
    int tid = threadIdx.x;                // 128
    for (int lin = tid; lin < B_SZ * D_T; lin += 128) sht[lin] = g_ht[lin];
    __syncthreads();
    int i = blockIdx.x;                   // 0..63
    int k = blockIdx.y * 128 + tid;       // 0..511
    float acc[B_SZ];
    #pragma unroll
    for (int b = 0; b < B_SZ; b++) acc[b] = 0.f;
    for (int j = 0; j < D_T; j++) {
        float w = __ldg(&trans_W[(i * D_T + j) * NWE + k]);
        #pragma unroll
        for (int b = 0; b < B_SZ; b++) acc[b] += sht[b * D_T + j] * w;
    }
    #pragma unroll
    for (int b = 0; b < B_SZ; b++) g_M[(b * D_T + i) * NWE + k] = acc[b];
}

// emb[n][e] = (U[text[n]] @ M_b^T + vb_b) @ dw_W^T + dw_b
__global__ void emb_kernel(const int* __restrict__ text, const float* __restrict__ U,
                           const float* __restrict__ dw_W, const float* __restrict__ dw_b) {
    extern __shared__ float MsT[];        // [512][65] padded transpose of M_b
    __shared__ float us[NWE];
    __shared__ float vecs[16][D_T];
    __shared__ float sp[4][D_T];
    int b   = blockIdx.x >> 3;
    int grp = blockIdx.x & 7;
    int tid = threadIdx.x;

    for (int lin = tid; lin < D_T * NWE; lin += 256) {
        int i = lin >> 9;
        int k = lin & 511;
        MsT[k * 65 + i] = g_M[(b * D_T + i) * NWE + k];
    }
    int i    = tid & 63;
    int part = tid >> 6;
    float vbv = 0.f;
    __syncthreads();
    if (part == 0) vbv = g_vb[b * D_T + i];

    for (int tt = 0; tt < 16; tt++) {
        int s = grp * 16 + tt;
        int n = s * B_SZ + b;
        int tok = text[n];
        __syncthreads();
        for (int k = tid; k < NWE; k += 256) us[k] = U[(size_t)tok * NWE + k];
        __syncthreads();
        float acc = 0.f;
        int k0 = part * 128;
        #pragma unroll 8
        for (int k = 0; k < 128; k++) acc += us[k0 + k] * MsT[(k0 + k) * 65 + i];
        sp[part][i] = acc;
        __syncthreads();
        if (part == 0) vecs[tt][i] = vbv + sp[0][i] + sp[1][i] + sp[2][i] + sp[3][i];
    }
    __syncthreads();

    float accs[16];
    for (int e = tid; e < NWE; e += 256) {
        float bias = dw_b[e];
        #pragma unroll
        for (int t = 0; t < 16; t++) accs[t] = bias;
        for (int i2 = 0; i2 < D_T; i2++) {
            float w = __ldg(&dw_W[e * D_T + i2]);
            #pragma unroll
            for (int t = 0; t < 16; t++) accs[t] += vecs[t][i2] * w;
        }
        #pragma unroll
        for (int t = 0; t < 16; t++) {
            int n = (grp * 16 + t) * B_SZ + b;
            g_emb[n * NWE + e] = accs[t];
        }
    }
}

// ====== fp16 split HMMA GEMM-NT: main f32-acc + corrections f16-acc ==========
// C = Ah*Bh (f32 acc) + [Ah*Bl + Al*Bh] (f16 acc, /2048) + bias[N]
// A[M,K], B[N,K] K-major fp16 (lo pre-scaled x2048).
// CTA tile 128x128, BK=64 (128B rows, XOR-swizzled), 3-stage cp.async pipeline,
// 8 warps (2M x 4N), warp tile 64x32, m16n8k16 via ldmatrix.x4.

#define HG_ARR   (16 * 1024)            // one 128x64 fp16 array
#define HG_STAGE (4 * HG_ARR)           // Ah, Al, Bh, Bl
#define HG_SMEM  (3 * HG_STAGE)         // 192KB

__device__ __forceinline__ void mma16816f(float* c, const uint32_t* a, const uint32_t* b) {
    asm volatile(
        "mma.sync.aligned.m16n8k16.row.col.f32.f16.f16.f32 "
        "{%0,%1,%2,%3},{%4,%5,%6,%7},{%8,%9},{%0,%1,%2,%3};"
        : "+f"(c[0]), "+f"(c[1]), "+f"(c[2]), "+f"(c[3])
        : "r"(a[0]), "r"(a[1]), "r"(a[2]), "r"(a[3]), "r"(b[0]), "r"(b[1]));
}

__device__ __forceinline__ void mma16816h(uint32_t* c, const uint32_t* a, const uint32_t* b) {
    asm volatile(
        "mma.sync.aligned.m16n8k16.row.col.f16.f16.f16.f16 "
        "{%0,%1},{%2,%3,%4,%5},{%6,%7},{%0,%1};"
        : "+r"(c[0]), "+r"(c[1])
        : "r"(a[0]), "r"(a[1]), "r"(a[2]), "r"(a[3]), "r"(b[0]), "r"(b[1]));
}

__device__ __forceinline__ void ldsm4(uint32_t* r, uint32_t addr) {
    asm volatile("ldmatrix.sync.aligned.m8n8.x4.shared.b16 {%0,%1,%2,%3}, [%4];"
                 : "=r"(r[0]), "=r"(r[1]), "=r"(r[2]), "=r"(r[3]) : "r"(addr));
}

__device__ __forceinline__ void cp16(uint32_t s, const void* g) {
    asm volatile("cp.async.cg.shared.global [%0], [%1], 16;" :: "r"(s), "l"(g));
}

__global__ __launch_bounds__(256, 1)
void hmma_gemm_nt(int M, int N, int K,
                  const __half* __restrict__ Ah, const __half* __restrict__ Al,
                  const __half* __restrict__ Bh, const __half* __restrict__ Bl,
                  const float* __restrict__ bias, float* __restrict__ C) {
    extern __shared__ __half sm[];
    const int tid  = threadIdx.x;
    const int lane = tid & 31;
    const int w    = tid >> 5;
    const int wm   = w >> 2;          // 0..1
    const int wn   = w & 3;           // 0..3
    const int bm   = blockIdx.x * 128;
    const int bn   = blockIdx.y * 128;
    const int NC   = K >> 6;

    uint32_t sbase = (uint32_t)__cvta_generic_to_shared(sm);

    // fill stage (chunk % 3): 4 arrays x 1024 16B segs; 4 segs/thread/array
    auto stage = [&](int chunk) {
        int k0 = chunk << 6;
        uint32_t sb = sbase + (chunk % 3) * HG_STAGE;
        #pragma unroll
        for (int r = 0; r < 4; r++) {
            int idx = tid + r * 256;
            int row = idx >> 3, ch = idx & 7;
            uint32_t so = (uint32_t)(row * 128 + (ch ^ (row & 7)) * 16);
            size_t ga = (size_t)(bm + row) * K + k0 + ch * 8;
            size_t gb = (size_t)(bn + row) * K + k0 + ch * 8;
            cp16(sb + 0 * HG_ARR + so, Ah + ga);
            cp16(sb + 1 * HG_ARR + so, Al + ga);
            cp16(sb + 2 * HG_ARR + so, Bh + gb);
            cp16(sb + 3 * HG_ARR + so, Bl + gb);
        }
        asm volatile("cp.async.commit_group;");
    };

    float    accf[4][4][4];
    uint32_t acch[4][4][2];
    #pragma unroll
    for (int mt = 0; mt < 4; mt++)
        #pragma unroll
        for (int nt = 0; nt < 4; nt++) {
            #pragma unroll
            for (int e = 0; e < 4; e++) accf[mt][nt][e] = 0.f;
            acch[mt][nt][0] = 0u;
            acch[mt][nt][1] = 0u;
        }

    stage(0);
    if (NC > 1) stage(1);
    if (NC > 2) stage(2);

    // per-lane ldmatrix row indices (fixed across chunks)
    const int arow = wm * 64 + (lane & 15);           // + mt*16
    const int asel = lane >> 4;                       // 16B chunk parity for A
    const int brow = wn * 32 + ((lane >> 4) << 3) + (lane & 7);   // + p*16
    const int bsel = (lane >> 3) & 1;

    for (int i = 0; i < NC; i++) {
        if (i + 3 <= NC - 1)      asm volatile("cp.async.wait_group 2;");
        else if (i + 2 <= NC - 1) asm volatile("cp.async.wait_group 1;");
        else                      asm volatile("cp.async.wait_group 0;");
        __syncthreads();

        uint32_t sb = sbase + (i % 3) * HG_STAGE;
        #pragma unroll
        for (int kk = 0; kk < 4; kk++) {
            uint32_t ah[4][4], al[4][4];
            #pragma unroll
            for (int mt = 0; mt < 4; mt++) {
                int r = arow + mt * 16;
                uint32_t ch = (uint32_t)((kk * 2 + asel) ^ (r & 7));
                uint32_t ad = sb + r * 128 + ch * 16;
                ldsm4(ah[mt], ad);
                ldsm4(al[mt], ad + HG_ARR);
            }
            uint32_t bh[4][2], bl[4][2];
            #pragma unroll
            for (int p = 0; p < 2; p++) {
                int n = brow + p * 16;
                uint32_t ch = (uint32_t)((kk * 2 + bsel) ^ (n & 7));
                uint32_t ad = sb + 2 * HG_ARR + n * 128 + ch * 16;
                uint32_t t0[4], t1[4];
                ldsm4(t0, ad);
                ldsm4(t1, ad + HG_ARR);
                bh[2 * p][0] = t0[0]; bh[2 * p][1] = t0[1];
                bh[2 * p + 1][0] = t0[2]; bh[2 * p + 1][1] = t0[3];
                bl[2 * p][0] = t1[0]; bl[2 * p][1] = t1[1];
                bl[2 * p + 1][0] = t1[2]; bl[2 * p + 1][1] = t1[3];
            }
            #pragma unroll
            for (int mt = 0; mt < 4; mt++)
                #pragma unroll
                for (int nt = 0; nt < 4; nt++) {
                    mma16816f(accf[mt][nt], ah[mt], bh[nt]);     // main, f32 acc
                    mma16816h(acch[mt][nt], ah[mt], bl[nt]);     // corr, f16 acc
                    mma16816h(acch[mt][nt], al[mt], bh[nt]);     // corr, f16 acc
                }
        }
        __syncthreads();
        if (i + 3 < NC) stage(i + 3);
    }

    // epilogue: C = main + corr/2048 + bias
    #pragma unroll
    for (int mt = 0; mt < 4; mt++) {
        int row = bm + wm * 64 + mt * 16 + (lane >> 2);
        #pragma unroll
        for (int nt = 0; nt < 4; nt++) {
            int col = bn + wn * 32 + nt * 8 + (lane & 3) * 2;
            float2 bb = *(const float2*)&bias[col];
            __half2 h01 = *(__half2*)&acch[mt][nt][0];
            __half2 h23 = *(__half2*)&acch[mt][nt][1];
            float2 c01 = __half22float2(h01);
            float2 c23 = __half22float2(h23);
            float2 v0 = make_float2(accf[mt][nt][0] + c01.x * INV_LO_SCALE + bb.x,
                                    accf[mt][nt][1] + c01.y * INV_LO_SCALE + bb.y);
            float2 v1 = make_float2(accf[mt][nt][2] + c23.x * INV_LO_SCALE + bb.x,
                                    accf[mt][nt][3] + c23.y * INV_LO_SCALE + bb.y);
            *(float2*)&C[(size_t)row * N + col] = v0;
            *(float2*)&C[(size_t)(row + 8) * N + col] = v1;
        }
    }
}

// ----------------------------- LSTM step kernel ------------------------------
// grid 128 blocks x 256 threads. warp per hidden unit u (8 u/block), lane = b.
#define LSTM_SMEM (1024 * 33 * 4 + 4 * 8 * 32 * 16)
__global__ __launch_bounds__(256)
void lstm_step_kernel(int t, int layer, int parity, const float* __restrict__ Whh) {
    extern __shared__ float hs[];   // [1024][33] padded + weight staging
    const float* xp = (layer ? g_xp1 : g_xp0) + (size_t)t * B_SZ * G4;
    float* outp     = (layer ? g_out1 : g_out0) + (size_t)t * B_SZ * H_RNN;
    const float* h_prev = g_h[layer][parity];
    float* h_next       = g_h[layer][parity ^ 1];
    float* c            = g_c[layer];
    int tid = threadIdx.x;

    for (int lin = tid; lin < B_SZ * H_RNN; lin += 256) {
        int b = lin >> 10;
        int k = lin & 1023;
        hs[k * 33 + b] = h_prev[lin];
    }
    __syncthreads();

    int lane = tid & 31;
    int w    = tid >> 5;
    int u    = blockIdx.x * 8 + w;
    int b    = lane;

    const float4* wi = (const float4*)(Whh + (size_t)u * H_RNN);
    const float4* wf = (const float4*)(Whh + (size_t)(H_RNN + u) * H_RNN);
    const float4* wg = (const float4*)(Whh + (size_t)(2 * H_RNN + u) * H_RNN);
    const float4* wo = (const float4*)(Whh + (size_t)(3 * H_RNN + u) * H_RNN);

    float4* sw  = (float4*)(hs + 1024 * 33);
    float4* swi = sw + (w * 4 + 0) * 32;
    float4* swf = sw + (w * 4 + 1) * 32;
    float4* swg = sw + (w * 4 + 2) * 32;
    float4* swo = sw + (w * 4 + 3) * 32;

    float si = 0.f, sf = 0.f, sg = 0.f, so = 0.f;
    for (int k0 = 0; k0 < H_RNN / 4; k0 += 32) {
        swi[lane] = __ldg(&wi[k0 + lane]);
        swf[lane] = __ldg(&wf[k0 + lane]);
        swg[lane] = __ldg(&wg[k0 + lane]);
        swo[lane] = __ldg(&wo[k0 + lane]);
        __syncwarp();
        #pragma unroll 8
        for (int q = 0; q < 32; q++) {
            int k = (k0 + q) * 4;
            float4 ai = swi[q];
            float4 af = swf[q];
            float4 ag = swg[q];
            float4 ao = swo[q];
            float h0 = hs[(k + 0) * 33 + b];
            float h1 = hs[(k + 1) * 33 + b];
            float h2 = hs[(k + 2) * 33 + b];
            float h3 = hs[(k + 3) * 33 + b];
            si += ai.x * h0 + ai.y * h1 + ai.z * h2 + ai.w * h3;
            sf += af.x * h0 + af.y * h1 + af.z * h2 + af.w * h3;
            sg += ag.x * h0 + ag.y * h1 + ag.z * h2 + ag.w * h3;
            so += ao.x * h0 + ao.y * h1 + ao.z * h2 + ao.w * h3;
        }
        __syncwarp();
    }
    si += xp[b * G4 + u];
    sf += xp[b * G4 + H_RNN + u];
    sg += xp[b * G4 + 2 * H_RNN + u];
    so += xp[b * G4 + 3 * H_RNN + u];

    float I = 1.f / (1.f + __expf(-si));
    float F = 1.f / (1.f + __expf(-sf));
    float G = tanhf(sg);
    float O = 1.f / (1.f + __expf(-so));
    int idx = b * H_RNN + u;
    float cv = F * c[idx] + I * G;
    c[idx] = cv;
    float hv = O * tanhf(cv);
    h_next[idx] = hv;
    outp[idx] = hv;
}

// --------------------------------- launcher ----------------------------------
extern "C" void kernel_launch(void* const* d_in, const int* in_sizes, int n_in,
                              void* d_out, int out_size) {
    const int*   text     = (const int*)d_in[0];
    const int*   timestep = (const int*)d_in[1];
    const float* U        = (const float*)d_in[2];
    const float* trans_W  = (const float*)d_in[3];
    const float* trans_b  = (const float*)d_in[4];
    const float* tc_W1    = (const float*)d_in[5];
    const float* tc_b1    = (const float*)d_in[6];
    const float* tc_W2    = (const float*)d_in[7];
    const float* tc_b2    = (const float*)d_in[8];
    const float* dw_W     = (const float*)d_in[9];
    const float* dw_b     = (const float*)d_in[10];
    const float* Wih0     = (const float*)d_in[11];
    const float* Whh0     = (const float*)d_in[12];
    const float* bih0     = (const float*)d_in[13];
    const float* bhh0     = (const float*)d_in[14];
    const float* Wih1     = (const float*)d_in[15];
    const float* Whh1     = (const float*)d_in[16];
    const float* bih1     = (const float*)d_in[17];
    const float* bhh1     = (const float*)d_in[18];
    const float* dec_W    = (const float*)d_in[19];
    const float* dec_b    = (const float*)d_in[20];
    float* out = (float*)d_out;

    float *p_emb, *p_xp0, *p_xp1, *p_out0, *p_out1, *p_gb0, *p_gb1;
    __half *p_Ah, *p_Al, *p_Bh, *p_Bl;
    cudaGetSymbolAddress((void**)&p_emb,  g_emb);
    cudaGetSymbolAddress((void**)&p_xp0,  g_xp0);
    cudaGetSymbolAddress((void**)&p_xp1,  g_xp1);
    cudaGetSymbolAddress((void**)&p_out0, g_out0);
    cudaGetSymbolAddress((void**)&p_out1, g_out1);
    cudaGetSymbolAddress((void**)&p_gb0,  g_gb0);
    cudaGetSymbolAddress((void**)&p_gb1,  g_gb1);
    cudaGetSymbolAddress((void**)&p_Ah,   g_Ah);
    cudaGetSymbolAddress((void**)&p_Al,   g_Al);
    cudaGetSymbolAddress((void**)&p_Bh,   g_Bh);
    cudaGetSymbolAddress((void**)&p_Bl,   g_Bl);

    cudaFuncSetAttribute(emb_kernel, cudaFuncAttributeMaxDynamicSharedMemorySize, 512 * 65 * 4);
    cudaFuncSetAttribute(lstm_step_kernel, cudaFuncAttributeMaxDynamicSharedMemorySize, LSTM_SMEM);
    cudaFuncSetAttribute(hmma_gemm_nt, cudaFuncAttributeMaxDynamicSharedMemorySize, HG_SMEM);

    zero_state_kernel<<<(B_SZ * H_RNN + 255) / 256, 256>>>();
    gbias_kernel<<<(G4 + 255) / 256, 256>>>(bih0, bhh0, bih1, bhh1);
    ht_kernel<<<B_SZ, D_T>>>(timestep, tc_W1, tc_b1, tc_W2, tc_b2, trans_b);
    M_kernel<<<dim3(D_T, 4), 128>>>(trans_W);
    emb_kernel<<<256, 256, 512 * 65 * 4>>>(text, U, dw_W, dw_b);

    int n4;
    // xp0 = emb @ Wih0^T + (bih0+bhh0)   [4096 x 4096], K=512
    n4 = NTOKR * NWE / 4;
    split_kernel<<<(n4 + 255) / 256, 256>>>((const float4*)p_emb, (uint2*)p_Ah, (uint2*)p_Al, n4);
    n4 = G4 * NWE / 4;
    split_kernel<<<(n4 + 255) / 256, 256>>>((const float4*)Wih0, (uint2*)p_Bh, (uint2*)p_Bl, n4);
    hmma_gemm_nt<<<dim3(NTOKR / 128, G4 / 128), 256, HG_SMEM>>>(
        NTOKR, G4, NWE, p_Ah, p_Al, p_Bh, p_Bl, p_gb0, p_xp0);

    for (int t = 0; t < S_LEN; t++)
        lstm_step_kernel<<<128, 256, LSTM_SMEM>>>(t, 0, t & 1, Whh0);

    // xp1 = out0 @ Wih1^T + (bih1+bhh1)  [4096 x 4096], K=1024
    n4 = NTOKR * H_RNN / 4;
    split_kernel<<<(n4 + 255) / 256, 256>>>((const float4*)p_out0, (uint2*)p_Ah, (uint2*)p_Al, n4);
    n4 = G4 * H_RNN / 4;
    split_kernel<<<(n4 + 255) / 256, 256>>>((const float4*)Wih1, (uint2*)p_Bh, (uint2*)p_Bl, n4);
    hmma_gemm_nt<<<dim3(NTOKR / 128, G4 / 128), 256, HG_SMEM>>>(
        NTOKR, G4, H_RNN, p_Ah, p_Al, p_Bh, p_Bl, p_gb1, p_xp1);

    for (int t = 0; t < S_LEN; t++)
        lstm_step_kernel<<<128, 256, LSTM_SMEM>>>(t, 1, t & 1, Whh1);

    // logits = out1 @ dec_W^T + dec_b    [4096 x 32000], K=1024
    n4 = NTOKR * H_RNN / 4;
    split_kernel<<<(n4 + 255) / 256, 256>>>((const float4*)p_out1, (uint2*)p_Ah, (uint2*)p_Al, n4);
    n4 = NVOCAB * H_RNN / 4;
    split_kernel<<<(n4 + 255) / 256, 256>>>((const float4*)dec_W, (uint2*)p_Bh, (uint2*)p_Bl, n4);
    hmma_gemm_nt<<<dim3(NTOKR / 128, NVOCAB / 128), 256, HG_SMEM>>>(
        NTOKR, NVOCAB, H_RNN, p_Ah, p_Al, p_Bh, p_Bl, dec_b, out);
}

// round 8
// speedup vs baseline: 1.0464x; 1.0464x over previous
#include <cuda_runtime.h>
#include <cuda_bf16.h>
#include <cuda_fp16.h>
#include <math.h>
#include <stdint.h>

#define S_LEN  128
#define B_SZ   32
#define NTOKR  4096      // S*B rows
#define NWE    512
#define D_T    64
#define H_RNN  1024
#define G4     4096      // 4*H
#define NVOCAB 32000

#define LO_SCALE      2048.0f
#define INV_LO_SCALE  4.8828125e-4f
#define A_SCALE       16384.0f          // 2^14: lifts out1 (~5e-7) into fp16 normal range
#define INV_A_SCALE   6.103515625e-5f

// ------------------- scratch (device globals; no allocs allowed) -------------
__device__ float g_ht[B_SZ * D_T];
__device__ float g_vb[B_SZ * D_T];
__device__ float g_M[B_SZ * D_T * NWE];          // [b][i][k]  4MB
__device__ float g_emb[NTOKR * NWE];             // 8MB
__device__ float g_xp0[(size_t)NTOKR * G4];      // 64MB
__device__ float g_xp1[(size_t)NTOKR * G4];      // 64MB
__device__ float g_out0[NTOKR * H_RNN];          // 16MB
__device__ float g_out1[NTOKR * H_RNN];          // 16MB
__device__ float g_h[2][2][B_SZ * H_RNN];        // [layer][parity]
__device__ float g_c[2][B_SZ * H_RNN];
__device__ float g_gb0[G4];
__device__ float g_gb1[G4];
// 16-bit split scratch (bf16 for xp GEMMs; reinterpreted as fp16 for decoder)
__device__ __nv_bfloat16 g_Ah[(size_t)NTOKR * H_RNN];        // 8MB
__device__ __nv_bfloat16 g_Al[(size_t)NTOKR * H_RNN];        // 8MB
__device__ __nv_bfloat16 g_Bh[(size_t)NVOCAB * H_RNN];       // 62.5MB
__device__ __nv_bfloat16 g_Bl[(size_t)NVOCAB * H_RNN];       // 62.5MB

// ------------------------------- utility kernels -----------------------------
__global__ void zero_state_kernel() {
    int i = blockIdx.x * blockDim.x + threadIdx.x;
    if (i < B_SZ * H_RNN) {
        g_h[0][0][i] = 0.f; g_h[0][1][i] = 0.f;
        g_h[1][0][i] = 0.f; g_h[1][1][i] = 0.f;
        g_c[0][i] = 0.f;    g_c[1][i] = 0.f;
    }
}

__global__ void gbias_kernel(const float* __restrict__ bih0, const float* __restrict__ bhh0,
                             const float* __restrict__ bih1, const float* __restrict__ bhh1) {
    int g = blockIdx.x * blockDim.x + threadIdx.x;
    if (g < G4) {
        g_gb0[g] = bih0[g] + bhh0[g];
        g_gb1[g] = bih1[g] + bhh1[g];
    }
}

// fp32 -> bf16 hi + bf16 lo split (4 elements per thread) — xp GEMM operands
__global__ void split_bf16_kernel(const float4* __restrict__ X, uint2* __restrict__ Hi,
                                  uint2* __restrict__ Lo, int n4) {
    int i = blockIdx.x * 256 + threadIdx.x;
    if (i >= n4) return;
    float4 v = X[i];
    __nv_bfloat16 h0 = __float2bfloat16(v.x);
    __nv_bfloat16 h1 = __float2bfloat16(v.y);
    __nv_bfloat16 h2 = __float2bfloat16(v.z);
    __nv_bfloat16 h3 = __float2bfloat16(v.w);
    __nv_bfloat16 l0 = __float2bfloat16(v.x - __bfloat162float(h0));
    __nv_bfloat16 l1 = __float2bfloat16(v.y - __bfloat162float(h1));
    __nv_bfloat16 l2 = __float2bfloat16(v.z - __bfloat162float(h2));
    __nv_bfloat16 l3 = __float2bfloat16(v.w - __bfloat162float(h3));
    uint2 ph, pl;
    ph.x = (uint32_t)__bfloat16_as_ushort(h0) | ((uint32_t)__bfloat16_as_ushort(h1) << 16);
    ph.y = (uint32_t)__bfloat16_as_ushort(h2) | ((uint32_t)__bfloat16_as_ushort(h3) << 16);
    pl.x = (uint32_t)__bfloat16_as_ushort(l0) | ((uint32_t)__bfloat16_as_ushort(l1) << 16);
    pl.y = (uint32_t)__bfloat16_as_ushort(l2) | ((uint32_t)__bfloat16_as_ushort(l3) << 16);
    Hi[i] = ph;
    Lo[i] = pl;
}

// fp32 -> fp16(x * 2^14) single convert — decoder A (out1 is ~5e-7: must scale
// into fp16 normal range or subnormal flush destroys 8 bits of precision)
__global__ void convA_f16s_kernel(const float4* __restrict__ X, uint2* __restrict__ O, int n4) {
    int i = blockIdx.x * 256 + threadIdx.x;
    if (i >= n4) return;
    float4 v = X[i];
    uint2 p;
    p.x = (uint32_t)__half_as_ushort(__float2half(v.x * A_SCALE))
        | ((uint32_t)__half_as_ushort(__float2half(v.y * A_SCALE)) << 16);
    p.y = (uint32_t)__half_as_ushort(__float2half(v.z * A_SCALE))
        | ((uint32_t)__half_as_ushort(__float2half(v.w * A_SCALE)) << 16);
    O[i] = p;
}

// fp32 -> fp16 hi + fp16 (lo*2048) split — decoder B (dec_W ~0.02, fp16-normal)
__global__ void splitB_f16_kernel(const float4* __restrict__ X, uint2* __restrict__ Hi,
                                  uint2* __restrict__ Lo, int n4) {
    int i = blockIdx.x * 256 + threadIdx.x;
    if (i >= n4) return;
    float4 v = X[i];
    __half h0 = __float2half(v.x);
    __half h1 = __float2half(v.y);
    __half h2 = __float2half(v.z);
    __half h3 = __float2half(v.w);
    __half l0 = __float2half((v.x - __half2float(h0)) * LO_SCALE);
    __half l1 = __float2half((v.y - __half2float(h1)) * LO_SCALE);
    __half l2 = __float2half((v.z - __half2float(h2)) * LO_SCALE);
    __half l3 = __float2half((v.w - __half2float(h3)) * LO_SCALE);
    uint2 ph, pl;
    ph.x = (uint32_t)__half_as_ushort(h0) | ((uint32_t)__half_as_ushort(h1) << 16);
    ph.y = (uint32_t)__half_as_ushort(h2) | ((uint32_t)__half_as_ushort(h3) << 16);
    pl.x = (uint32_t)__half_as_ushort(l0) | ((uint32_t)__half_as_ushort(l1) << 16);
    pl.y = (uint32_t)__half_as_ushort(l2) | ((uint32_t)__half_as_ushort(l3) << 16);
    Hi[i] = ph;
    Lo[i] = pl;
}

// ht[b][i] = tanh(W2 @ tanh(ts*W1 + b1) + b2); vb[b][i] = sum_j trans_b[i*64+j]*ht[b][j]
__global__ void ht_kernel(const int* __restrict__ timestep,
                          const float* __restrict__ W1, const float* __restrict__ b1,
                          const float* __restrict__ W2, const float* __restrict__ b2,
                          const float* __restrict__ trans_b) {
    int b = blockIdx.x;
    int j = threadIdx.x;          // 64 threads
    float ts = (float)timestep[b] / 100.0f;
    __shared__ float h1[D_T];
    __shared__ float hts[D_T];
    h1[j] = tanhf(ts * W1[j] + b1[j]);
    __syncthreads();
    float acc = b2[j];
    #pragma unroll 8
    for (int k = 0; k < D_T; k++) acc += W2[j * D_T + k] * h1[k];
    float htv = tanhf(acc);
    g_ht[b * D_T + j] = htv;
    hts[j] = htv;
    __syncthreads();
    float vb = 0.f;
    #pragma unroll 8
    for (int k = 0; k < D_T; k++) vb += trans_b[j * D_T + k] * hts[k];
    g_vb[b * D_T + j] = vb;
}

// M[b][i][k] = sum_j ht[b][j] * trans_W[(i*64+j)*512 + k]
__global__ void M_kernel(const float* __restrict__ trans_W) {
    __shared__ float sht[B_SZ * D_T];
    int tid = threadIdx.x;                // 128
    for (int lin = tid; lin < B_SZ * D_T; lin += 128) sht[lin] = g_ht[lin];
    __syncthreads();
    int i = blockIdx.x;                   // 0..63
    int k = blockIdx.y * 128 + tid;       // 0..511
    float acc[B_SZ];
    #pragma unroll
    for (int b = 0; b < B_SZ; b++) acc[b] = 0.f;
    for (int j = 0; j < D_T; j++) {
        float w = __ldg(&trans_W[(i * D_T + j) * NWE + k]);
        #pragma unroll
        for (int b = 0; b < B_SZ; b++) acc[b] += sht[b * D_T + j] * w;
    }
    #pragma unroll
    for (int b = 0; b < B_SZ; b++) g_M[(b * D_T + i) * NWE + k] = acc[b];
}

// emb[n][e] = (U[text[n]] @ M_b^T + vb_b) @ dw_W^T + dw_b
__global__ void emb_kernel(const int* __restrict__ text, const float* __restrict__ U,
                           const float* __restrict__ dw_W, const float* __restrict__ dw_b) {
    extern __shared__ float MsT[];        // [512][65] padded transpose of M_b
    __shared__ float us[NWE];
    __shared__ float vecs[16][D_T];
    __shared__ float sp[4][D_T];
    int b   = blockIdx.x >> 3;
    int grp = blockIdx.x & 7;
    int tid = threadIdx.x;

    for (int lin = tid; lin < D_T * NWE; lin += 256) {
        int i = lin >> 9;
        int k = lin & 511;
        MsT[k * 65 + i] = g_M[(b * D_T + i) * NWE + k];
    }
    int i    = tid & 63;
    int part = tid >> 6;
    float vbv = 0.f;
    __syncthreads();
    if (part == 0) vbv = g_vb[b * D_T + i];

    for (int tt = 0; tt < 16; tt++) {
        int s = grp * 16 + tt;
        int n = s * B_SZ + b;
        int tok = text[n];
        __syncthreads();
        for (int k = tid; k < NWE; k += 256) us[k] = U[(size_t)tok * NWE + k];
        __syncthreads();
        float acc = 0.f;
        int k0 = part * 128;
        #pragma unroll 8
        for (int k = 0; k < 128; k++) acc += us[k0 + k] * MsT[(k0 + k) * 65 + i];
        sp[part][i] = acc;
        __syncthreads();
        if (part == 0) vecs[tt][i] = vbv + sp[0][i] + sp[1][i] + sp[2][i] + sp[3][i];
    }
    __syncthreads();

    float accs[16];
    for (int e = tid; e < NWE; e += 256) {
        float bias = dw_b[e];
        #pragma unroll
        for (int t = 0; t < 16; t++) accs[t] = bias;
        for (int i2 = 0; i2 < D_T; i2++) {
            float w = __ldg(&dw_W[e * D_T + i2]);
            #pragma unroll
            for (int t = 0; t < 16; t++) accs[t] += vecs[t][i2] * w;
        }
        #pragma unroll
        for (int t = 0; t < 16; t++) {
            int n = (grp * 16 + t) * B_SZ + b;
            g_emb[n * NWE + e] = accs[t];
        }
    }
}

// ================= shared GEMM machinery =====================================
#define HG_ARR   (16 * 1024)            // one 128x64 16-bit array

__device__ __forceinline__ void mma_bf16(float* c, const uint32_t* a, const uint32_t* b) {
    asm volatile(
        "mma.sync.aligned.m16n8k16.row.col.f32.bf16.bf16.f32 "
        "{%0,%1,%2,%3},{%4,%5,%6,%7},{%8,%9},{%0,%1,%2,%3};"
        : "+f"(c[0]), "+f"(c[1]), "+f"(c[2]), "+f"(c[3])
        : "r"(a[0]), "r"(a[1]), "r"(a[2]), "r"(a[3]), "r"(b[0]), "r"(b[1]));
}

__device__ __forceinline__ void mma_f16(float* c, const uint32_t* a, const uint32_t* b) {
    asm volatile(
        "mma.sync.aligned.m16n8k16.row.col.f32.f16.f16.f32 "
        "{%0,%1,%2,%3},{%4,%5,%6,%7},{%8,%9},{%0,%1,%2,%3};"
        : "+f"(c[0]), "+f"(c[1]), "+f"(c[2]), "+f"(c[3])
        : "r"(a[0]), "r"(a[1]), "r"(a[2]), "r"(a[3]), "r"(b[0]), "r"(b[1]));
}

__device__ __forceinline__ void ldsm4(uint32_t* r, uint32_t addr) {
    asm volatile("ldmatrix.sync.aligned.m8n8.x4.shared.b16 {%0,%1,%2,%3}, [%4];"
                 : "=r"(r[0]), "=r"(r[1]), "=r"(r[2]), "=r"(r[3]) : "r"(addr));
}

__device__ __forceinline__ void cp16(uint32_t s, const void* g) {
    asm volatile("cp.async.cg.shared.global [%0], [%1], 16;" :: "r"(s), "l"(g));
}

// ============ bf16 3-product GEMM-NT (xp GEMMs; proven rel_err ~1e-5) ========
// C = Ah*Bh + Ah*Bl + Al*Bh + bias[N]; bf16 hi/lo splits, f32 accumulation.
#define HG_STAGE4 (4 * HG_ARR)
#define HG_SMEM4  (3 * HG_STAGE4)       // 192KB

__global__ __launch_bounds__(256, 1)
void gemm_bf16_3p(int M, int N, int K,
                  const __nv_bfloat16* __restrict__ Ah, const __nv_bfloat16* __restrict__ Al,
                  const __nv_bfloat16* __restrict__ Bh, const __nv_bfloat16* __restrict__ Bl,
                  const float* __restrict__ bias, float* __restrict__ C) {
    extern __shared__ __nv_bfloat16 smb[];
    const int tid  = threadIdx.x;
    const int lane = tid & 31;
    const int w    = tid >> 5;
    const int wm   = w >> 2;
    const int wn   = w & 3;
    const int bm   = blockIdx.x * 128;
    const int bn   = blockIdx.y * 128;
    const int NC   = K >> 6;

    uint32_t sbase = (uint32_t)__cvta_generic_to_shared(smb);

    auto stage = [&](int chunk) {
        int k0 = chunk << 6;
        uint32_t sb = sbase + (chunk % 3) * HG_STAGE4;
        #pragma unroll
        for (int r = 0; r < 4; r++) {
            int idx = tid + r * 256;
            int row = idx >> 3, ch = idx & 7;
            uint32_t so = (uint32_t)(row * 128 + (ch ^ (row & 7)) * 16);
            size_t ga = (size_t)(bm + row) * K + k0 + ch * 8;
            size_t gb = (size_t)(bn + row) * K + k0 + ch * 8;
            cp16(sb + 0 * HG_ARR + so, Ah + ga);
            cp16(sb + 1 * HG_ARR + so, Al + ga);
            cp16(sb + 2 * HG_ARR + so, Bh + gb);
            cp16(sb + 3 * HG_ARR + so, Bl + gb);
        }
        asm volatile("cp.async.commit_group;");
    };

    float acc[4][4][4];
    #pragma unroll
    for (int mt = 0; mt < 4; mt++)
        #pragma unroll
        for (int nt = 0; nt < 4; nt++)
            #pragma unroll
            for (int e = 0; e < 4; e++) acc[mt][nt][e] = 0.f;

    stage(0);
    if (NC > 1) stage(1);
    if (NC > 2) stage(2);

    const int arow = wm * 64 + (lane & 15);
    const int asel = lane >> 4;
    const int brow = wn * 32 + ((lane >> 4) << 3) + (lane & 7);
    const int bsel = (lane >> 3) & 1;

    for (int i = 0; i < NC; i++) {
        if (i + 3 <= NC - 1)      asm volatile("cp.async.wait_group 2;");
        else if (i + 2 <= NC - 1) asm volatile("cp.async.wait_group 1;");
        else                      asm volatile("cp.async.wait_group 0;");
        __syncthreads();

        uint32_t sb = sbase + (i % 3) * HG_STAGE4;
        #pragma unroll
        for (int kk = 0; kk < 4; kk++) {
            uint32_t ah[4][4], al[4][4];
            #pragma unroll
            for (int mt = 0; mt < 4; mt++) {
                int r = arow + mt * 16;
                uint32_t ch = (uint32_t)((kk * 2 + asel) ^ (r & 7));
                uint32_t ad = sb + r * 128 + ch * 16;
                ldsm4(ah[mt], ad);
                ldsm4(al[mt], ad + HG_ARR);
            }
            uint32_t bh[4][2], bl[4][2];
            #pragma unroll
            for (int p = 0; p < 2; p++) {
                int n = brow + p * 16;
                uint32_t ch = (uint32_t)((kk * 2 + bsel) ^ (n & 7));
                uint32_t ad = sb + 2 * HG_ARR + n * 128 + ch * 16;
                uint32_t t0[4], t1[4];
                ldsm4(t0, ad);
                ldsm4(t1, ad + HG_ARR);
                bh[2 * p][0] = t0[0]; bh[2 * p][1] = t0[1];
                bh[2 * p + 1][0] = t0[2]; bh[2 * p + 1][1] = t0[3];
                bl[2 * p][0] = t1[0]; bl[2 * p][1] = t1[1];
                bl[2 * p + 1][0] = t1[2]; bl[2 * p + 1][1] = t1[3];
            }
            #pragma unroll
            for (int mt = 0; mt < 4; mt++)
                #pragma unroll
                for (int nt = 0; nt < 4; nt++) {
                    mma_bf16(acc[mt][nt], ah[mt], bh[nt]);
                    mma_bf16(acc[mt][nt], ah[mt], bl[nt]);
                    mma_bf16(acc[mt][nt], al[mt], bh[nt]);
                }
        }
        __syncthreads();
        if (i + 3 < NC) stage(i + 3);
    }

    #pragma unroll
    for (int mt = 0; mt < 4; mt++) {
        int row = bm + wm * 64 + mt * 16 + (lane >> 2);
        #pragma unroll
        for (int nt = 0; nt < 4; nt++) {
            int col = bn + wn * 32 + nt * 8 + (lane & 3) * 2;
            float2 bb = *(const float2*)&bias[col];
            float2 v0 = make_float2(acc[mt][nt][0] + bb.x, acc[mt][nt][1] + bb.y);
            float2 v1 = make_float2(acc[mt][nt][2] + bb.x, acc[mt][nt][3] + bb.y);
            *(float2*)&C[(size_t)row * N + col] = v0;
            *(float2*)&C[(size_t)(row + 8) * N + col] = v1;
        }
    }
}

// ====== fp16 2-product GEMM-NT (decoder): C = (A_s*Bh + A_s*Bl/2048)/2^14 ====
// A_s = fp16(A * 2^14) single; B split fp16 hi + lo*2048. f32 accumulation.
#define HG_STAGE3 (3 * HG_ARR)
#define HG_SMEM3  (3 * HG_STAGE3)       // 144KB

__global__ __launch_bounds__(256, 1)
void gemm_f16_2p(int M, int N, int K,
                 const __half* __restrict__ As,
                 const __half* __restrict__ Bh, const __half* __restrict__ Bl,
                 const float* __restrict__ bias, float* __restrict__ C) {
    extern __shared__ __half smh[];
    const int tid  = threadIdx.x;
    const int lane = tid & 31;
    const int w    = tid >> 5;
    const int wm   = w >> 2;
    const int wn   = w & 3;
    const int bm   = blockIdx.x * 128;
    const int bn   = blockIdx.y * 128;
    const int NC   = K >> 6;

    uint32_t sbase = (uint32_t)__cvta_generic_to_shared(smh);

    auto stage = [&](int chunk) {
        int k0 = chunk << 6;
        uint32_t sb = sbase + (chunk % 3) * HG_STAGE3;
        #pragma unroll
        for (int r = 0; r < 4; r++) {
            int idx = tid + r * 256;
            int row = idx >> 3, ch = idx & 7;
            uint32_t so = (uint32_t)(row * 128 + (ch ^ (row & 7)) * 16);
            size_t ga = (size_t)(bm + row) * K + k0 + ch * 8;
            size_t gb = (size_t)(bn + row) * K + k0 + ch * 8;
            cp16(sb + 0 * HG_ARR + so, As + ga);
            cp16(sb + 1 * HG_ARR + so, Bh + gb);
            cp16(sb + 2 * HG_ARR + so, Bl + gb);
        }
        asm volatile("cp.async.commit_group;");
    };

    float accf[4][4][4];   // main product (A_s * Bh)
    float accc[4][4][4];   // correction (A_s * Bl), scale 1/2048
    #pragma unroll
    for (int mt = 0; mt < 4; mt++)
        #pragma unroll
        for (int nt = 0; nt < 4; nt++)
            #pragma unroll
            for (int e = 0; e < 4; e++) { accf[mt][nt][e] = 0.f; accc[mt][nt][e] = 0.f; }

    stage(0);
    if (NC > 1) stage(1);
    if (NC > 2) stage(2);

    const int arow = wm * 64 + (lane & 15);
    const int asel = lane >> 4;
    const int brow = wn * 32 + ((lane >> 4) << 3) + (lane & 7);
    const int bsel = (lane >> 3) & 1;

    for (int i = 0; i < NC; i++) {
        if (i + 3 <= NC - 1)      asm volatile("cp.async.wait_group 2;");
        else if (i + 2 <= NC - 1) asm volatile("cp.async.wait_group 1;");
        else                      asm volatile("cp.async.wait_group 0;");
        __syncthreads();

        uint32_t sb = sbase + (i % 3) * HG_STAGE3;
        #pragma unroll
        for (int kk = 0; kk < 4; kk++) {
            uint32_t ah[4][4];
            #pragma unroll
            for (int mt = 0; mt < 4; mt++) {
                int r = arow + mt * 16;
                uint32_t ch = (uint32_t)((kk * 2 + asel) ^ (r & 7));
                ldsm4(ah[mt], sb + r * 128 + ch * 16);
            }
            uint32_t bh[4][2], bl[4][2];
            #pragma unroll
            for (int p = 0; p < 2; p++) {
                int n = brow + p * 16;
                uint32_t ch = (uint32_t)((kk * 2 + bsel) ^ (n & 7));
                uint32_t ad = sb + 1 * HG_ARR + n * 128 + ch * 16;
                uint32_t t0[4], t1[4];
                ldsm4(t0, ad);
                ldsm4(t1, ad + HG_ARR);
                bh[2 * p][0] = t0[0]; bh[2 * p][1] = t0[1];
                bh[2 * p + 1][0] = t0[2]; bh[2 * p + 1][1] = t0[3];
                bl[2 * p][0] = t1[0]; bl[2 * p][1] = t1[1];
                bl[2 * p + 1][0] = t1[2]; bl[2 * p + 1][1] = t1[3];
            }
            #pragma unroll
            for (int mt = 0; mt < 4; mt++)
                #pragma unroll
                for (int nt = 0; nt < 4; nt++) {
                    mma_f16(accf[mt][nt], ah[mt], bh[nt]);
                    mma_f16(accc[mt][nt], ah[mt], bl[nt]);
                }
        }
        __syncthreads();
        if (i + 3 < NC) stage(i + 3);
    }

    // C = (accf + accc/2048) / 2^14 + bias
    #pragma unroll
    for (int mt = 0; mt < 4; mt++) {
        int row = bm + wm * 64 + mt * 16 + (lane >> 2);
        #pragma unroll
        for (int nt = 0; nt < 4; nt++) {
            int col = bn + wn * 32 + nt * 8 + (lane & 3) * 2;
            float2 bb = *(const float2*)&bias[col];
            float2 v0 = make_float2(
                (accf[mt][nt][0] + accc[mt][nt][0] * INV_LO_SCALE) * INV_A_SCALE + bb.x,
                (accf[mt][nt][1] + accc[mt][nt][1] * INV_LO_SCALE) * INV_A_SCALE + bb.y);
            float2 v1 = make_float2(
                (accf[mt][nt][2] + accc[mt][nt][2] * INV_LO_SCALE) * INV_A_SCALE + bb.x,
                (accf[mt][nt][3] + accc[mt][nt][3] * INV_LO_SCALE) * INV_A_SCALE + bb.y);
            *(float2*)&C[(size_t)row * N + col] = v0;
            *(float2*)&C[(size_t)(row + 8) * N + col] = v1;
        }
    }
}

// ----------------------------- LSTM step kernel ------------------------------
// grid 128 blocks x 256 threads. warp per hidden unit u (8 u/block), lane = b.
#define LSTM_SMEM (1024 * 33 * 4 + 4 * 8 * 32 * 16)
__global__ __launch_bounds__(256)
void lstm_step_kernel(int t, int layer, int parity, const float* __restrict__ Whh) {
    extern __shared__ float hs[];   // [1024][33] padded + weight staging
    const float* xp = (layer ? g_xp1 : g_xp0) + (size_t)t * B_SZ * G4;
    float* outp     = (layer ? g_out1 : g_out0) + (size_t)t * B_SZ * H_RNN;
    const float* h_prev = g_h[layer][parity];
    float* h_next       = g_h[layer][parity ^ 1];
    float* c            = g_c[layer];
    int tid = threadIdx.x;

    for (int lin = tid; lin < B_SZ * H_RNN; lin += 256) {
        int b = lin >> 10;
        int k = lin & 1023;
        hs[k * 33 + b] = h_prev[lin];
    }
    __syncthreads();

    int lane = tid & 31;
    int w    = tid >> 5;
    int u    = blockIdx.x * 8 + w;
    int b    = lane;

    const float4* wi = (const float4*)(Whh + (size_t)u * H_RNN);
    const float4* wf = (const float4*)(Whh + (size_t)(H_RNN + u) * H_RNN);
    const float4* wg = (const float4*)(Whh + (size_t)(2 * H_RNN + u) * H_RNN);
    const float4* wo = (const float4*)(Whh + (size_t)(3 * H_RNN + u) * H_RNN);

    float4* sw  = (float4*)(hs + 1024 * 33);
    float4* swi = sw + (w * 4 + 0) * 32;
    float4* swf = sw + (w * 4 + 1) * 32;
    float4* swg = sw + (w * 4 + 2) * 32;
    float4* swo = sw + (w * 4 + 3) * 32;

    float si = 0.f, sf = 0.f, sg = 0.f, so = 0.f;
    for (int k0 = 0; k0 < H_RNN / 4; k0 += 32) {
        swi[lane] = __ldg(&wi[k0 + lane]);
        swf[lane] = __ldg(&wf[k0 + lane]);
        swg[lane] = __ldg(&wg[k0 + lane]);
        swo[lane] = __ldg(&wo[k0 + lane]);
        __syncwarp();
        #pragma unroll 8
        for (int q = 0; q < 32; q++) {
            int k = (k0 + q) * 4;
            float4 ai = swi[q];
            float4 af = swf[q];
            float4 ag = swg[q];
            float4 ao = swo[q];
            float h0 = hs[(k + 0) * 33 + b];
            float h1 = hs[(k + 1) * 33 + b];
            float h2 = hs[(k + 2) * 33 + b];
            float h3 = hs[(k + 3) * 33 + b];
            si += ai.x * h0 + ai.y * h1 + ai.z * h2 + ai.w * h3;
            sf += af.x * h0 + af.y * h1 + af.z * h2 + af.w * h3;
            sg += ag.x * h0 + ag.y * h1 + ag.z * h2 + ag.w * h3;
            so += ao.x * h0 + ao.y * h1 + ao.z * h2 + ao.w * h3;
        }
        __syncwarp();
    }
    si += xp[b * G4 + u];
    sf += xp[b * G4 + H_RNN + u];
    sg += xp[b * G4 + 2 * H_RNN + u];
    so += xp[b * G4 + 3 * H_RNN + u];

    float I = 1.f / (1.f + __expf(-si));
    float F = 1.f / (1.f + __expf(-sf));
    float G = tanhf(sg);
    float O = 1.f / (1.f + __expf(-so));
    int idx = b * H_RNN + u;
    float cv = F * c[idx] + I * G;
    c[idx] = cv;
    float hv = O * tanhf(cv);
    h_next[idx] = hv;
    outp[idx] = hv;
}

// --------------------------------- launcher ----------------------------------
extern "C" void kernel_launch(void* const* d_in, const int* in_sizes, int n_in,
                              void* d_out, int out_size) {
    const int*   text     = (const int*)d_in[0];
    const int*   timestep = (const int*)d_in[1];
    const float* U        = (const float*)d_in[2];
    const float* trans_W  = (const float*)d_in[3];
    const float* trans_b  = (const float*)d_in[4];
    const float* tc_W1    = (const float*)d_in[5];
    const float* tc_b1    = (const float*)d_in[6];
    const float* tc_W2    = (const float*)d_in[7];
    const float* tc_b2    = (const float*)d_in[8];
    const float* dw_W     = (const float*)d_in[9];
    const float* dw_b     = (const float*)d_in[10];
    const float* Wih0     = (const float*)d_in[11];
    const float* Whh0     = (const float*)d_in[12];
    const float* bih0     = (const float*)d_in[13];
    const float* bhh0     = (const float*)d_in[14];
    const float* Wih1     = (const float*)d_in[15];
    const float* Whh1     = (const float*)d_in[16];
    const float* bih1     = (const float*)d_in[17];
    const float* bhh1     = (const float*)d_in[18];
    const float* dec_W    = (const float*)d_in[19];
    const float* dec_b    = (const float*)d_in[20];
    float* out = (float*)d_out;

    float *p_emb, *p_xp0, *p_xp1, *p_out0, *p_out1, *p_gb0, *p_gb1;
    __nv_bfloat16 *p_Ah, *p_Al, *p_Bh, *p_Bl;
    cudaGetSymbolAddress((void**)&p_emb,  g_emb);
    cudaGetSymbolAddress((void**)&p_xp0,  g_xp0);
    cudaGetSymbolAddress((void**)&p_xp1,  g_xp1);
    cudaGetSymbolAddress((void**)&p_out0, g_out0);
    cudaGetSymbolAddress((void**)&p_out1, g_out1);
    cudaGetSymbolAddress((void**)&p_gb0,  g_gb0);
    cudaGetSymbolAddress((void**)&p_gb1,  g_gb1);
    cudaGetSymbolAddress((void**)&p_Ah,   g_Ah);
    cudaGetSymbolAddress((void**)&p_Al,   g_Al);
    cudaGetSymbolAddress((void**)&p_Bh,   g_Bh);
    cudaGetSymbolAddress((void**)&p_Bl,   g_Bl);

    cudaFuncSetAttribute(emb_kernel, cudaFuncAttributeMaxDynamicSharedMemorySize, 512 * 65 * 4);
    cudaFuncSetAttribute(lstm_step_kernel, cudaFuncAttributeMaxDynamicSharedMemorySize, LSTM_SMEM);
    cudaFuncSetAttribute(gemm_bf16_3p, cudaFuncAttributeMaxDynamicSharedMemorySize, HG_SMEM4);
    cudaFuncSetAttribute(gemm_f16_2p,  cudaFuncAttributeMaxDynamicSharedMemorySize, HG_SMEM3);

    zero_state_kernel<<<(B_SZ * H_RNN + 255) / 256, 256>>>();
    gbias_kernel<<<(G4 + 255) / 256, 256>>>(bih0, bhh0, bih1, bhh1);
    ht_kernel<<<B_SZ, D_T>>>(timestep, tc_W1, tc_b1, tc_W2, tc_b2, trans_b);
    M_kernel<<<dim3(D_T, 4), 128>>>(trans_W);
    emb_kernel<<<256, 256, 512 * 65 * 4>>>(text, U, dw_W, dw_b);

    int n4;
    // xp0 = emb @ Wih0^T + (bih0+bhh0)   [4096 x 4096], K=512   (bf16 3-product)
    n4 = NTOKR * NWE / 4;
    split_bf16_kernel<<<(n4 + 255) / 256, 256>>>((const float4*)p_emb, (uint2*)p_Ah, (uint2*)p_Al, n4);
    n4 = G4 * NWE / 4;
    split_bf16_kernel<<<(n4 + 255) / 256, 256>>>((const float4*)Wih0, (uint2*)p_Bh, (uint2*)p_Bl, n4);
    gemm_bf16_3p<<<dim3(NTOKR / 128, G4 / 128), 256, HG_SMEM4>>>(
        NTOKR, G4, NWE, p_Ah, p_Al, p_Bh, p_Bl, p_gb0, p_xp0);

    for (int t = 0; t < S_LEN; t++)
        lstm_step_kernel<<<128, 256, LSTM_SMEM>>>(t, 0, t & 1, Whh0);

    // xp1 = out0 @ Wih1^T + (bih1+bhh1)  [4096 x 4096], K=1024  (bf16 3-product)
    n4 = NTOKR * H_RNN / 4;
    split_bf16_kernel<<<(n4 + 255) / 256, 256>>>((const float4*)p_out0, (uint2*)p_Ah, (uint2*)p_Al, n4);
    n4 = G4 * H_RNN / 4;
    split_bf16_kernel<<<(n4 + 255) / 256, 256>>>((const float4*)Wih1, (uint2*)p_Bh, (uint2*)p_Bl, n4);
    gemm_bf16_3p<<<dim3(NTOKR / 128, G4 / 128), 256, HG_SMEM4>>>(
        NTOKR, G4, H_RNN, p_Ah, p_Al, p_Bh, p_Bl, p_gb1, p_xp1);

    for (int t = 0; t < S_LEN; t++)
        lstm_step_kernel<<<128, 256, LSTM_SMEM>>>(t, 1, t & 1, Whh1);

    // logits = out1 @ dec_W^T + dec_b    [4096 x 32000], K=1024
    // fp16 2-product: A = fp16(out1 * 2^14) (scaled out of subnormal range),
    // B = dec_W split fp16 hi + lo*2048. Decoder-stage noise amplification ~1.
    n4 = NTOKR * H_RNN / 4;
    convA_f16s_kernel<<<(n4 + 255) / 256, 256>>>((const float4*)p_out1, (uint2*)p_Ah, n4);
    n4 = NVOCAB * H_RNN / 4;
    splitB_f16_kernel<<<(n4 + 255) / 256, 256>>>((const float4*)dec_W, (uint2*)p_Bh, (uint2*)p_Bl, n4);
    gemm_f16_2p<<<dim3(NTOKR / 128, NVOCAB / 128), 256, HG_SMEM3>>>(
        NTOKR, NVOCAB, H_RNN, (const __half*)p_Ah, (const __half*)p_Bh, (const __half*)p_Bl,
        dec_b, out);
}

// round 9
// speedup vs baseline: 1.2861x; 1.2291x over previous
#include <cuda_runtime.h>
#include <cuda_bf16.h>
#include <cuda_fp16.h>
#include <math.h>
#include <stdint.h>

#define S_LEN  128
#define B_SZ   32
#define NTOKR  4096      // S*B rows
#define NWE    512
#define D_T    64
#define H_RNN  1024
#define G4     4096      // 4*H
#define NVOCAB 32000

#define A_SCALE       16384.0f          // 2^14: lifts out1 (~5e-7) into fp16 normal range
#define INV_A_SCALE   6.103515625e-5f

// ------------------- scratch (device globals; no allocs allowed) -------------
__device__ float g_ht[B_SZ * D_T];
__device__ float g_vb[B_SZ * D_T];
__device__ float g_M[B_SZ * D_T * NWE];          // [b][i][k]  4MB
__device__ float g_emb[NTOKR * NWE];             // 8MB
__device__ float g_xp0[(size_t)NTOKR * G4];      // 64MB
__device__ float g_xp1[(size_t)NTOKR * G4];      // 64MB
__device__ float g_out0[NTOKR * H_RNN];          // 16MB
__device__ float g_out1[NTOKR * H_RNN];          // 16MB
__device__ float g_h[2][2][B_SZ * H_RNN];        // [layer][parity]
__device__ float g_c[2][B_SZ * H_RNN];
__device__ float g_gb0[G4];
__device__ float g_gb1[G4];
// 16-bit split scratch (bf16 for xp GEMMs; reinterpreted as fp16 for decoder)
__device__ __nv_bfloat16 g_Ah[(size_t)NTOKR * H_RNN];        // 8MB
__device__ __nv_bfloat16 g_Al[(size_t)NTOKR * H_RNN];        // 8MB
__device__ __nv_bfloat16 g_Bh[(size_t)NVOCAB * H_RNN];       // 62.5MB
__device__ __nv_bfloat16 g_Bl[(size_t)NVOCAB * H_RNN];       // 62.5MB (unused by decoder now)

// ------------------------------- utility kernels -----------------------------
__global__ void zero_state_kernel() {
    int i = blockIdx.x * blockDim.x + threadIdx.x;
    if (i < B_SZ * H_RNN) {
        g_h[0][0][i] = 0.f; g_h[0][1][i] = 0.f;
        g_h[1][0][i] = 0.f; g_h[1][1][i] = 0.f;
        g_c[0][i] = 0.f;    g_c[1][i] = 0.f;
    }
}

__global__ void gbias_kernel(const float* __restrict__ bih0, const float* __restrict__ bhh0,
                             const float* __restrict__ bih1, const float* __restrict__ bhh1) {
    int g = blockIdx.x * blockDim.x + threadIdx.x;
    if (g < G4) {
        g_gb0[g] = bih0[g] + bhh0[g];
        g_gb1[g] = bih1[g] + bhh1[g];
    }
}

// fp32 -> bf16 hi + bf16 lo split (4 elements per thread) — xp GEMM operands
__global__ void split_bf16_kernel(const float4* __restrict__ X, uint2* __restrict__ Hi,
                                  uint2* __restrict__ Lo, int n4) {
    int i = blockIdx.x * 256 + threadIdx.x;
    if (i >= n4) return;
    float4 v = X[i];
    __nv_bfloat16 h0 = __float2bfloat16(v.x);
    __nv_bfloat16 h1 = __float2bfloat16(v.y);
    __nv_bfloat16 h2 = __float2bfloat16(v.z);
    __nv_bfloat16 h3 = __float2bfloat16(v.w);
    __nv_bfloat16 l0 = __float2bfloat16(v.x - __bfloat162float(h0));
    __nv_bfloat16 l1 = __float2bfloat16(v.y - __bfloat162float(h1));
    __nv_bfloat16 l2 = __float2bfloat16(v.z - __bfloat162float(h2));
    __nv_bfloat16 l3 = __float2bfloat16(v.w - __bfloat162float(h3));
    uint2 ph, pl;
    ph.x = (uint32_t)__bfloat16_as_ushort(h0) | ((uint32_t)__bfloat16_as_ushort(h1) << 16);
    ph.y = (uint32_t)__bfloat16_as_ushort(h2) | ((uint32_t)__bfloat16_as_ushort(h3) << 16);
    pl.x = (uint32_t)__bfloat16_as_ushort(l0) | ((uint32_t)__bfloat16_as_ushort(l1) << 16);
    pl.y = (uint32_t)__bfloat16_as_ushort(l2) | ((uint32_t)__bfloat16_as_ushort(l3) << 16);
    Hi[i] = ph;
    Lo[i] = pl;
}

// fp32 -> fp16(x * 2^14) single convert — decoder A (out1 ~5e-7 must be lifted
// out of fp16 subnormal range or flush destroys 8 bits of precision)
__global__ void convA_f16s_kernel(const float4* __restrict__ X, uint2* __restrict__ O, int n4) {
    int i = blockIdx.x * 256 + threadIdx.x;
    if (i >= n4) return;
    float4 v = X[i];
    uint2 p;
    p.x = (uint32_t)__half_as_ushort(__float2half(v.x * A_SCALE))
        | ((uint32_t)__half_as_ushort(__float2half(v.y * A_SCALE)) << 16);
    p.y = (uint32_t)__half_as_ushort(__float2half(v.z * A_SCALE))
        | ((uint32_t)__half_as_ushort(__float2half(v.w * A_SCALE)) << 16);
    O[i] = p;
}

// fp32 -> fp16 single convert — decoder B (dec_W ~0.02, comfortably fp16-normal)
__global__ void convB_f16_kernel(const float4* __restrict__ X, uint2* __restrict__ O, int n4) {
    int i = blockIdx.x * 256 + threadIdx.x;
    if (i >= n4) return;
    float4 v = X[i];
    uint2 p;
    p.x = (uint32_t)__half_as_ushort(__float2half(v.x))
        | ((uint32_t)__half_as_ushort(__float2half(v.y)) << 16);
    p.y = (uint32_t)__half_as_ushort(__float2half(v.z))
        | ((uint32_t)__half_as_ushort(__float2half(v.w)) << 16);
    O[i] = p;
}

// ht[b][i] = tanh(W2 @ tanh(ts*W1 + b1) + b2); vb[b][i] = sum_j trans_b[i*64+j]*ht[b][j]
__global__ void ht_kernel(const int* __restrict__ timestep,
                          const float* __restrict__ W1, const float* __restrict__ b1,
                          const float* __restrict__ W2, const float* __restrict__ b2,
                          const float* __restrict__ trans_b) {
    int b = blockIdx.x;
    int j = threadIdx.x;          // 64 threads
    float ts = (float)timestep[b] / 100.0f;
    __shared__ float h1[D_T];
    __shared__ float hts[D_T];
    h1[j] = tanhf(ts * W1[j] + b1[j]);
    __syncthreads();
    float acc = b2[j];
    #pragma unroll 8
    for (int k = 0; k < D_T; k++) acc += W2[j * D_T + k] * h1[k];
    float htv = tanhf(acc);
    g_ht[b * D_T + j] = htv;
    hts[j] = htv;
    __syncthreads();
    float vb = 0.f;
    #pragma unroll 8
    for (int k = 0; k < D_T; k++) vb += trans_b[j * D_T + k] * hts[k];
    g_vb[b * D_T + j] = vb;
}

// M[b][i][k] = sum_j ht[b][j] * trans_W[(i*64+j)*512 + k]
__global__ void M_kernel(const float* __restrict__ trans_W) {
    __shared__ float sht[B_SZ * D_T];
    int tid = threadIdx.x;                // 128
    for (int lin = tid; lin < B_SZ * D_T; lin += 128) sht[lin] = g_ht[lin];
    __syncthreads();
    int i = blockIdx.x;                   // 0..63
    int k = blockIdx.y * 128 + tid;       // 0..511
    float acc[B_SZ];
    #pragma unroll
    for (int b = 0; b < B_SZ; b++) acc[b] = 0.f;
    for (int j = 0; j < D_T; j++) {
        float w = __ldg(&trans_W[(i * D_T + j) * NWE + k]);
        #pragma unroll
        for (int b = 0; b < B_SZ; b++) acc[b] += sht[b * D_T + j] * w;
    }
    #pragma unroll
    for (int b = 0; b < B_SZ; b++) g_M[(b * D_T + i) * NWE + k] = acc[b];
}

// emb[n][e] = (U[text[n]] @ M_b^T + vb_b) @ dw_W^T + dw_b
__global__ void emb_kernel(const int* __restrict__ text, const float* __restrict__ U,
                           const float* __restrict__ dw_W, const float* __restrict__ dw_b) {
    extern __shared__ float MsT[];        // [512][65] padded transpose of M_b
    __shared__ float us[NWE];
    __shared__ float vecs[16][D_T];
    __shared__ float sp[4][D_T];
    int b   = blockIdx.x >> 3;
    int grp = blockIdx.x & 7;
    int tid = threadIdx.x;

    for (int lin = tid; lin < D_T * NWE; lin += 256) {
        int i = lin >> 9;
        int k = lin & 511;
        MsT[k * 65 + i] = g_M[(b * D_T + i) * NWE + k];
    }
    int i    = tid & 63;
    int part = tid >> 6;
    float vbv = 0.f;
    __syncthreads();
    if (part == 0) vbv = g_vb[b * D_T + i];

    for (int tt = 0; tt < 16; tt++) {
        int s = grp * 16 + tt;
        int n = s * B_SZ + b;
        int tok = text[n];
        __syncthreads();
        for (int k = tid; k < NWE; k += 256) us[k] = U[(size_t)tok * NWE + k];
        __syncthreads();
        float acc = 0.f;
        int k0 = part * 128;
        #pragma unroll 8
        for (int k = 0; k < 128; k++) acc += us[k0 + k] * MsT[(k0 + k) * 65 + i];
        sp[part][i] = acc;
        __syncthreads();
        if (part == 0) vecs[tt][i] = vbv + sp[0][i] + sp[1][i] + sp[2][i] + sp[3][i];
    }
    __syncthreads();

    float accs[16];
    for (int e = tid; e < NWE; e += 256) {
        float bias = dw_b[e];
        #pragma unroll
        for (int t = 0; t < 16; t++) accs[t] = bias;
        for (int i2 = 0; i2 < D_T; i2++) {
            float w = __ldg(&dw_W[e * D_T + i2]);
            #pragma unroll
            for (int t = 0; t < 16; t++) accs[t] += vecs[t][i2] * w;
        }
        #pragma unroll
        for (int t = 0; t < 16; t++) {
            int n = (grp * 16 + t) * B_SZ + b;
            g_emb[n * NWE + e] = accs[t];
        }
    }
}

// ================= shared GEMM machinery =====================================
#define HG_ARR   (16 * 1024)            // one 128x64 16-bit array

__device__ __forceinline__ void mma_bf16(float* c, const uint32_t* a, const uint32_t* b) {
    asm volatile(
        "mma.sync.aligned.m16n8k16.row.col.f32.bf16.bf16.f32 "
        "{%0,%1,%2,%3},{%4,%5,%6,%7},{%8,%9},{%0,%1,%2,%3};"
        : "+f"(c[0]), "+f"(c[1]), "+f"(c[2]), "+f"(c[3])
        : "r"(a[0]), "r"(a[1]), "r"(a[2]), "r"(a[3]), "r"(b[0]), "r"(b[1]));
}

__device__ __forceinline__ void mma_f16(float* c, const uint32_t* a, const uint32_t* b) {
    asm volatile(
        "mma.sync.aligned.m16n8k16.row.col.f32.f16.f16.f32 "
        "{%0,%1,%2,%3},{%4,%5,%6,%7},{%8,%9},{%0,%1,%2,%3};"
        : "+f"(c[0]), "+f"(c[1]), "+f"(c[2]), "+f"(c[3])
        : "r"(a[0]), "r"(a[1]), "r"(a[2]), "r"(a[3]), "r"(b[0]), "r"(b[1]));
}

__device__ __forceinline__ void ldsm4(uint32_t* r, uint32_t addr) {
    asm volatile("ldmatrix.sync.aligned.m8n8.x4.shared.b16 {%0,%1,%2,%3}, [%4];"
                 : "=r"(r[0]), "=r"(r[1]), "=r"(r[2]), "=r"(r[3]) : "r"(addr));
}

__device__ __forceinline__ void cp16(uint32_t s, const void* g) {
    asm volatile("cp.async.cg.shared.global [%0], [%1], 16;" :: "r"(s), "l"(g));
}

// ============ bf16 3-product GEMM-NT (xp GEMMs; proven rel_err ~1e-5) ========
// C = Ah*Bh + Ah*Bl + Al*Bh + bias[N]; bf16 hi/lo splits, f32 accumulation.
#define HG_STAGE4 (4 * HG_ARR)
#define HG_SMEM4  (3 * HG_STAGE4)       // 192KB

__global__ __launch_bounds__(256, 1)
void gemm_bf16_3p(int M, int N, int K,
                  const __nv_bfloat16* __restrict__ Ah, const __nv_bfloat16* __restrict__ Al,
                  const __nv_bfloat16* __restrict__ Bh, const __nv_bfloat16* __restrict__ Bl,
                  const float* __restrict__ bias, float* __restrict__ C) {
    extern __shared__ __nv_bfloat16 smb[];
    const int tid  = threadIdx.x;
    const int lane = tid & 31;
    const int w    = tid >> 5;
    const int wm   = w >> 2;
    const int wn   = w & 3;
    const int bm   = blockIdx.x * 128;
    const int bn   = blockIdx.y * 128;
    const int NC   = K >> 6;

    uint32_t sbase = (uint32_t)__cvta_generic_to_shared(smb);

    auto stage = [&](int chunk) {
        int k0 = chunk << 6;
        uint32_t sb = sbase + (chunk % 3) * HG_STAGE4;
        #pragma unroll
        for (int r = 0; r < 4; r++) {
            int idx = tid + r * 256;
            int row = idx >> 3, ch = idx & 7;
            uint32_t so = (uint32_t)(row * 128 + (ch ^ (row & 7)) * 16);
            size_t ga = (size_t)(bm + row) * K + k0 + ch * 8;
            size_t gb = (size_t)(bn + row) * K + k0 + ch * 8;
            cp16(sb + 0 * HG_ARR + so, Ah + ga);
            cp16(sb + 1 * HG_ARR + so, Al + ga);
            cp16(sb + 2 * HG_ARR + so, Bh + gb);
            cp16(sb + 3 * HG_ARR + so, Bl + gb);
        }
        asm volatile("cp.async.commit_group;");
    };

    float acc[4][4][4];
    #pragma unroll
    for (int mt = 0; mt < 4; mt++)
        #pragma unroll
        for (int nt = 0; nt < 4; nt++)
            #pragma unroll
            for (int e = 0; e < 4; e++) acc[mt][nt][e] = 0.f;

    stage(0);
    if (NC > 1) stage(1);
    if (NC > 2) stage(2);

    const int arow = wm * 64 + (lane & 15);
    const int asel = lane >> 4;
    const int brow = wn * 32 + ((lane >> 4) << 3) + (lane & 7);
    const int bsel = (lane >> 3) & 1;

    for (int i = 0; i < NC; i++) {
        if (i + 3 <= NC - 1)      asm volatile("cp.async.wait_group 2;");
        else if (i + 2 <= NC - 1) asm volatile("cp.async.wait_group 1;");
        else                      asm volatile("cp.async.wait_group 0;");
        __syncthreads();

        uint32_t sb = sbase + (i % 3) * HG_STAGE4;
        #pragma unroll
        for (int kk = 0; kk < 4; kk++) {
            uint32_t ah[4][4], al[4][4];
            #pragma unroll
            for (int mt = 0; mt < 4; mt++) {
                int r = arow + mt * 16;
                uint32_t ch = (uint32_t)((kk * 2 + asel) ^ (r & 7));
                uint32_t ad = sb + r * 128 + ch * 16;
                ldsm4(ah[mt], ad);
                ldsm4(al[mt], ad + HG_ARR);
            }
            uint32_t bh[4][2], bl[4][2];
            #pragma unroll
            for (int p = 0; p < 2; p++) {
                int n = brow + p * 16;
                uint32_t ch = (uint32_t)((kk * 2 + bsel) ^ (n & 7));
                uint32_t ad = sb + 2 * HG_ARR + n * 128 + ch * 16;
                uint32_t t0[4], t1[4];
                ldsm4(t0, ad);
                ldsm4(t1, ad + HG_ARR);
                bh[2 * p][0] = t0[0]; bh[2 * p][1] = t0[1];
                bh[2 * p + 1][0] = t0[2]; bh[2 * p + 1][1] = t0[3];
                bl[2 * p][0] = t1[0]; bl[2 * p][1] = t1[1];
                bl[2 * p + 1][0] = t1[2]; bl[2 * p + 1][1] = t1[3];
            }
            #pragma unroll
            for (int mt = 0; mt < 4; mt++)
                #pragma unroll
                for (int nt = 0; nt < 4; nt++) {
                    mma_bf16(acc[mt][nt], ah[mt], bh[nt]);
                    mma_bf16(acc[mt][nt], ah[mt], bl[nt]);
                    mma_bf16(acc[mt][nt], al[mt], bh[nt]);
                }
        }
        __syncthreads();
        if (i + 3 < NC) stage(i + 3);
    }

    #pragma unroll
    for (int mt = 0; mt < 4; mt++) {
        int row = bm + wm * 64 + mt * 16 + (lane >> 2);
        #pragma unroll
        for (int nt = 0; nt < 4; nt++) {
            int col = bn + wn * 32 + nt * 8 + (lane & 3) * 2;
            float2 bb = *(const float2*)&bias[col];
            float2 v0 = make_float2(acc[mt][nt][0] + bb.x, acc[mt][nt][1] + bb.y);
            float2 v1 = make_float2(acc[mt][nt][2] + bb.x, acc[mt][nt][3] + bb.y);
            *(float2*)&C[(size_t)row * N + col] = v0;
            *(float2*)&C[(size_t)(row + 8) * N + col] = v1;
        }
    }
}

// ====== fp16 1-product GEMM-NT (decoder): C = A_s * B / 2^14 + bias ==========
// A_s = fp16(A * 2^14); B = fp16(dec_W). 2 arrays/stage -> 96KB -> 2 CTAs/SM.
#define HG_STAGE2 (2 * HG_ARR)
#define HG_SMEM2  (3 * HG_STAGE2)       // 96KB

__global__ __launch_bounds__(256, 2)
void gemm_f16_1p(int M, int N, int K,
                 const __half* __restrict__ As, const __half* __restrict__ B,
                 const float* __restrict__ bias, float* __restrict__ C) {
    extern __shared__ __half smh[];
    const int tid  = threadIdx.x;
    const int lane = tid & 31;
    const int w    = tid >> 5;
    const int wm   = w >> 2;
    const int wn   = w & 3;
    const int bm   = blockIdx.x * 128;
    const int bn   = blockIdx.y * 128;
    const int NC   = K >> 6;

    uint32_t sbase = (uint32_t)__cvta_generic_to_shared(smh);

    auto stage = [&](int chunk) {
        int k0 = chunk << 6;
        uint32_t sb = sbase + (chunk % 3) * HG_STAGE2;
        #pragma unroll
        for (int r = 0; r < 4; r++) {
            int idx = tid + r * 256;
            int row = idx >> 3, ch = idx & 7;
            uint32_t so = (uint32_t)(row * 128 + (ch ^ (row & 7)) * 16);
            size_t ga = (size_t)(bm + row) * K + k0 + ch * 8;
            size_t gb = (size_t)(bn + row) * K + k0 + ch * 8;
            cp16(sb + 0 * HG_ARR + so, As + ga);
            cp16(sb + 1 * HG_ARR + so, B + gb);
        }
        asm volatile("cp.async.commit_group;");
    };

    float acc[4][4][4];
    #pragma unroll
    for (int mt = 0; mt < 4; mt++)
        #pragma unroll
        for (int nt = 0; nt < 4; nt++)
            #pragma unroll
            for (int e = 0; e < 4; e++) acc[mt][nt][e] = 0.f;

    stage(0);
    if (NC > 1) stage(1);
    if (NC > 2) stage(2);

    const int arow = wm * 64 + (lane & 15);
    const int asel = lane >> 4;
    const int brow = wn * 32 + ((lane >> 4) << 3) + (lane & 7);
    const int bsel = (lane >> 3) & 1;

    for (int i = 0; i < NC; i++) {
        if (i + 3 <= NC - 1)      asm volatile("cp.async.wait_group 2;");
        else if (i + 2 <= NC - 1) asm volatile("cp.async.wait_group 1;");
        else                      asm volatile("cp.async.wait_group 0;");
        __syncthreads();

        uint32_t sb = sbase + (i % 3) * HG_STAGE2;
        #pragma unroll
        for (int kk = 0; kk < 4; kk++) {
            uint32_t ah[4][4];
            #pragma unroll
            for (int mt = 0; mt < 4; mt++) {
                int r = arow + mt * 16;
                uint32_t ch = (uint32_t)((kk * 2 + asel) ^ (r & 7));
                ldsm4(ah[mt], sb + r * 128 + ch * 16);
            }
            uint32_t bf[4][2];
            #pragma unroll
            for (int p = 0; p < 2; p++) {
                int n = brow + p * 16;
                uint32_t ch = (uint32_t)((kk * 2 + bsel) ^ (n & 7));
                uint32_t t0[4];
                ldsm4(t0, sb + 1 * HG_ARR + n * 128 + ch * 16);
                bf[2 * p][0] = t0[0]; bf[2 * p][1] = t0[1];
                bf[2 * p + 1][0] = t0[2]; bf[2 * p + 1][1] = t0[3];
            }
            #pragma unroll
            for (int mt = 0; mt < 4; mt++)
                #pragma unroll
                for (int nt = 0; nt < 4; nt++)
                    mma_f16(acc[mt][nt], ah[mt], bf[nt]);
        }
        __syncthreads();
        if (i + 3 < NC) stage(i + 3);
    }

    // C = acc / 2^14 + bias
    #pragma unroll
    for (int mt = 0; mt < 4; mt++) {
        int row = bm + wm * 64 + mt * 16 + (lane >> 2);
        #pragma unroll
        for (int nt = 0; nt < 4; nt++) {
            int col = bn + wn * 32 + nt * 8 + (lane & 3) * 2;
            float2 bb = *(const float2*)&bias[col];
            float2 v0 = make_float2(acc[mt][nt][0] * INV_A_SCALE + bb.x,
                                    acc[mt][nt][1] * INV_A_SCALE + bb.y);
            float2 v1 = make_float2(acc[mt][nt][2] * INV_A_SCALE + bb.x,
                                    acc[mt][nt][3] * INV_A_SCALE + bb.y);
            *(float2*)&C[(size_t)row * N + col] = v0;
            *(float2*)&C[(size_t)(row + 8) * N + col] = v1;
        }
    }
}

// ----------------------------- LSTM step kernel ------------------------------
// grid 128 blocks x 256 threads. warp per hidden unit u (8 u/block), lane = b.
// Weight LDGs double-buffered in registers so L2/DRAM latency overlaps compute.
#define LSTM_SMEM (1024 * 33 * 4 + 4 * 8 * 32 * 16)
__global__ __launch_bounds__(256)
void lstm_step_kernel(int t, int layer, int parity, const float* __restrict__ Whh) {
    extern __shared__ float hs[];   // [1024][33] padded + weight staging
    const float* xp = (layer ? g_xp1 : g_xp0) + (size_t)t * B_SZ * G4;
    float* outp     = (layer ? g_out1 : g_out0) + (size_t)t * B_SZ * H_RNN;
    const float* h_prev = g_h[layer][parity];
    float* h_next       = g_h[layer][parity ^ 1];
    float* c            = g_c[layer];
    int tid = threadIdx.x;

    for (int lin = tid; lin < B_SZ * H_RNN; lin += 256) {
        int b = lin >> 10;
        int k = lin & 1023;
        hs[k * 33 + b] = h_prev[lin];
    }

    int lane = tid & 31;
    int w    = tid >> 5;
    int u    = blockIdx.x * 8 + w;
    int b    = lane;

    const float4* wi = (const float4*)(Whh + (size_t)u * H_RNN);
    const float4* wf = (const float4*)(Whh + (size_t)(H_RNN + u) * H_RNN);
    const float4* wg = (const float4*)(Whh + (size_t)(2 * H_RNN + u) * H_RNN);
    const float4* wo = (const float4*)(Whh + (size_t)(3 * H_RNN + u) * H_RNN);

    float4* sw  = (float4*)(hs + 1024 * 33);
    float4* swi = sw + (w * 4 + 0) * 32;
    float4* swf = sw + (w * 4 + 1) * 32;
    float4* swg = sw + (w * 4 + 2) * 32;
    float4* swo = sw + (w * 4 + 3) * 32;

    // prefetch chunk 0 weights while h staging completes
    float4 ni = __ldg(&wi[lane]);
    float4 nf = __ldg(&wf[lane]);
    float4 ng = __ldg(&wg[lane]);
    float4 no = __ldg(&wo[lane]);
    __syncthreads();

    float si = 0.f, sf = 0.f, sg = 0.f, so = 0.f;
    #pragma unroll 1
    for (int cchunk = 0; cchunk < 8; cchunk++) {
        int k0 = cchunk * 32;
        swi[lane] = ni; swf[lane] = nf; swg[lane] = ng; swo[lane] = no;
        __syncwarp();
        if (cchunk < 7) {                      // prefetch next chunk during compute
            ni = __ldg(&wi[k0 + 32 + lane]);
            nf = __ldg(&wf[k0 + 32 + lane]);
            ng = __ldg(&wg[k0 + 32 + lane]);
            no = __ldg(&wo[k0 + 32 + lane]);
        }
        #pragma unroll 8
        for (int q = 0; q < 32; q++) {
            int k = (k0 + q) * 4;
            float4 ai = swi[q];
            float4 af = swf[q];
            float4 ag = swg[q];
            float4 ao = swo[q];
            float h0 = hs[(k + 0) * 33 + b];
            float h1 = hs[(k + 1) * 33 + b];
            float h2 = hs[(k + 2) * 33 + b];
            float h3 = hs[(k + 3) * 33 + b];
            si += ai.x * h0 + ai.y * h1 + ai.z * h2 + ai.w * h3;
            sf += af.x * h0 + af.y * h1 + af.z * h2 + af.w * h3;
            sg += ag.x * h0 + ag.y * h1 + ag.z * h2 + ag.w * h3;
            so += ao.x * h0 + ao.y * h1 + ao.z * h2 + ao.w * h3;
        }
        __syncwarp();
    }
    si += xp[b * G4 + u];
    sf += xp[b * G4 + H_RNN + u];
    sg += xp[b * G4 + 2 * H_RNN + u];
    so += xp[b * G4 + 3 * H_RNN + u];

    float I = 1.f / (1.f + __expf(-si));
    float F = 1.f / (1.f + __expf(-sf));
    float G = tanhf(sg);
    float O = 1.f / (1.f + __expf(-so));
    int idx = b * H_RNN + u;
    float cv = F * c[idx] + I * G;
    c[idx] = cv;
    float hv = O * tanhf(cv);
    h_next[idx] = hv;
    outp[idx] = hv;
}

// --------------------------------- launcher ----------------------------------
extern "C" void kernel_launch(void* const* d_in, const int* in_sizes, int n_in,
                              void* d_out, int out_size) {
    const int*   text     = (const int*)d_in[0];
    const int*   timestep = (const int*)d_in[1];
    const float* U        = (const float*)d_in[2];
    const float* trans_W  = (const float*)d_in[3];
    const float* trans_b  = (const float*)d_in[4];
    const float* tc_W1    = (const float*)d_in[5];
    const float* tc_b1    = (const float*)d_in[6];
    const float* tc_W2    = (const float*)d_in[7];
    const float* tc_b2    = (const float*)d_in[8];
    const float* dw_W     = (const float*)d_in[9];
    const float* dw_b     = (const float*)d_in[10];
    const float* Wih0     = (const float*)d_in[11];
    const float* Whh0     = (const float*)d_in[12];
    const float* bih0     = (const float*)d_in[13];
    const float* bhh0     = (const float*)d_in[14];
    const float* Wih1     = (const float*)d_in[15];
    const float* Whh1     = (const float*)d_in[16];
    const float* bih1     = (const float*)d_in[17];
    const float* bhh1     = (const float*)d_in[18];
    const float* dec_W    = (const float*)d_in[19];
    const float* dec_b    = (const float*)d_in[20];
    float* out = (float*)d_out;

    float *p_emb, *p_xp0, *p_xp1, *p_out0, *p_out1, *p_gb0, *p_gb1;
    __nv_bfloat16 *p_Ah, *p_Al, *p_Bh, *p_Bl;
    cudaGetSymbolAddress((void**)&p_emb,  g_emb);
    cudaGetSymbolAddress((void**)&p_xp0,  g_xp0);
    cudaGetSymbolAddress((void**)&p_xp1,  g_xp1);
    cudaGetSymbolAddress((void**)&p_out0, g_out0);
    cudaGetSymbolAddress((void**)&p_out1, g_out1);
    cudaGetSymbolAddress((void**)&p_gb0,  g_gb0);
    cudaGetSymbolAddress((void**)&p_gb1,  g_gb1);
    cudaGetSymbolAddress((void**)&p_Ah,   g_Ah);
    cudaGetSymbolAddress((void**)&p_Al,   g_Al);
    cudaGetSymbolAddress((void**)&p_Bh,   g_Bh);
    cudaGetSymbolAddress((void**)&p_Bl,   g_Bl);

    cudaFuncSetAttribute(emb_kernel, cudaFuncAttributeMaxDynamicSharedMemorySize, 512 * 65 * 4);
    cudaFuncSetAttribute(lstm_step_kernel, cudaFuncAttributeMaxDynamicSharedMemorySize, LSTM_SMEM);
    cudaFuncSetAttribute(gemm_bf16_3p, cudaFuncAttributeMaxDynamicSharedMemorySize, HG_SMEM4);
    cudaFuncSetAttribute(gemm_f16_1p,  cudaFuncAttributeMaxDynamicSharedMemorySize, HG_SMEM2);

    zero_state_kernel<<<(B_SZ * H_RNN + 255) / 256, 256>>>();
    gbias_kernel<<<(G4 + 255) / 256, 256>>>(bih0, bhh0, bih1, bhh1);
    ht_kernel<<<B_SZ, D_T>>>(timestep, tc_W1, tc_b1, tc_W2, tc_b2, trans_b);
    M_kernel<<<dim3(D_T, 4), 128>>>(trans_W);
    emb_kernel<<<256, 256, 512 * 65 * 4>>>(text, U, dw_W, dw_b);

    int n4;
    // xp0 = emb @ Wih0^T + (bih0+bhh0)   [4096 x 4096], K=512   (bf16 3-product)
    n4 = NTOKR * NWE / 4;
    split_bf16_kernel<<<(n4 + 255) / 256, 256>>>((const float4*)p_emb, (uint2*)p_Ah, (uint2*)p_Al, n4);
    n4 = G4 * NWE / 4;
    split_bf16_kernel<<<(n4 + 255) / 256, 256>>>((const float4*)Wih0, (uint2*)p_Bh, (uint2*)p_Bl, n4);
    gemm_bf16_3p<<<dim3(NTOKR / 128, G4 / 128), 256, HG_SMEM4>>>(
        NTOKR, G4, NWE, p_Ah, p_Al, p_Bh, p_Bl, p_gb0, p_xp0);

    for (int t = 0; t < S_LEN; t++)
        lstm_step_kernel<<<128, 256, LSTM_SMEM>>>(t, 0, t & 1, Whh0);

    // xp1 = out0 @ Wih1^T + (bih1+bhh1)  [4096 x 4096], K=1024  (bf16 3-product)
    n4 = NTOKR * H_RNN / 4;
    split_bf16_kernel<<<(n4 + 255) / 256, 256>>>((const float4*)p_out0, (uint2*)p_Ah, (uint2*)p_Al, n4);
    n4 = G4 * H_RNN / 4;
    split_bf16_kernel<<<(n4 + 255) / 256, 256>>>((const float4*)Wih1, (uint2*)p_Bh, (uint2*)p_Bl, n4);
    gemm_bf16_3p<<<dim3(NTOKR / 128, G4 / 128), 256, HG_SMEM4>>>(
        NTOKR, G4, H_RNN, p_Ah, p_Al, p_Bh, p_Bl, p_gb1, p_xp1);

    for (int t = 0; t < S_LEN; t++)
        lstm_step_kernel<<<128, 256, LSTM_SMEM>>>(t, 1, t & 1, Whh1);

    // logits = out1 @ dec_W^T + dec_b    [4096 x 32000], K=1024
    // fp16 1-product: A = fp16(out1 * 2^14) (out of subnormal range),
    // B = fp16(dec_W). Decoder-stage rounding noise passes with gain ~1:
    // predicted rel_err ~= sqrt(2) * 2.08e-4 ~= 2.9e-4.
    n4 = NTOKR * H_RNN / 4;
    convA_f16s_kernel<<<(n4 + 255) / 256, 256>>>((const float4*)p_out1, (uint2*)p_Ah, n4);
    n4 = NVOCAB * H_RNN / 4;
    convB_f16_kernel<<<(n4 + 255) / 256, 256>>>((const float4*)dec_W, (uint2*)p_Bh, n4);
    gemm_f16_1p<<<dim3(NTOKR / 128, NVOCAB / 128), 256, HG_SMEM2>>>(
        NTOKR, NVOCAB, H_RNN, (const __half*)p_Ah, (const __half*)p_Bh, dec_b, out);
}